// round 2
// baseline (speedup 1.0000x reference)
#include <cuda_runtime.h>

#define HH 64
#define WW 64
#define HWN 4096
#define BB 32
#define CC 256
#define CPB 8   // channels per block in dot kernel

// Scratch: accumulated weight map A[b][h][w] (already scaled by 1/HW)
__device__ float g_A[BB * HWN];

__global__ void zero_A_kernel() {
    int i = blockIdx.x * blockDim.x + threadIdx.x;
    if (i < BB * HWN) g_A[i] = 0.0f;
}

// Scatter bilinear weights into the per-batch weight map.
// grid = (8 chunks, BB batches), 256 threads. Each block handles 512 pixels,
// accumulates into a private SMEM plane, then merges sparse nonzeros to global.
__global__ void __launch_bounds__(256) scatter_kernel(
    const float* __restrict__ offset, const float* __restrict__ ts_ptr)
{
    int b = blockIdx.y;
    int chunk = blockIdx.x;

    __shared__ float sA[HWN];
    for (int i = threadIdx.x; i < HWN; i += 256) sA[i] = 0.0f;
    __syncthreads();

    float ts = fminf(fmaxf(ts_ptr[0], 0.001f), 0.01f);
    const float inv = 1.0f / (float)HWN;
    const float* offy = offset + (size_t)b * 2 * HWN;
    const float* offx = offy + HWN;

    int p = chunk * 512 + threadIdx.x;
#pragma unroll
    for (int k = 0; k < 2; ++k, p += 256) {
        int i = p >> 6;
        int j = p & 63;
        float y = fminf(fmaxf((float)i + ts * offy[p] * 64.0f, 0.0f), 63.0f);
        float x = fminf(fmaxf((float)j + ts * offx[p] * 64.0f, 0.0f), 63.0f);
        int y0 = (int)floorf(y); if (y0 > 62) y0 = 62;
        int x0 = (int)floorf(x); if (x0 > 62) x0 = 62;
        float wy = y - (float)y0;
        float wx = x - (float)x0;
        float w00 = (1.0f - wy) * (1.0f - wx);
        float w01 = (1.0f - wy) * wx;
        float w10 = wy * (1.0f - wx);
        float w11 = wy * wx;
        int base = (y0 << 6) + x0;
        atomicAdd(&sA[base],          w00 * inv);
        atomicAdd(&sA[base + 1],      w01 * inv);
        atomicAdd(&sA[base + WW],     w10 * inv);
        atomicAdd(&sA[base + WW + 1], w11 * inv);
    }
    __syncthreads();

    float* Ab = g_A + (size_t)b * HWN;
    for (int i = threadIdx.x; i < HWN; i += 256) {
        float v = sA[i];
        if (v != 0.0f) atomicAdd(&Ab[i], v);
    }
}

// out[b,c] = dot(A[b], data[b,c]) — fully contiguous, LDG.128 streaming.
// grid = BB * (CC/CPB) blocks of 256 threads; each block: 1 batch, 8 channels.
__global__ void __launch_bounds__(256) dot_kernel(
    const float* __restrict__ data, float* __restrict__ out)
{
    int b  = blockIdx.x >> 5;   // CC/CPB = 32 channel-groups per batch
    int cg = blockIdx.x & 31;

    __shared__ float4 sA4[HWN / 4];
    const float4* Ab = (const float4*)(g_A + (size_t)b * HWN);
    for (int i = threadIdx.x; i < HWN / 4; i += 256) sA4[i] = Ab[i];
    __syncthreads();

    const float4* dp = (const float4*)(data + ((size_t)b * CC + (size_t)cg * CPB) * HWN);

    float acc[CPB];
#pragma unroll
    for (int ch = 0; ch < CPB; ++ch) acc[ch] = 0.0f;

#pragma unroll
    for (int ch = 0; ch < CPB; ++ch) {
        const float4* d4 = dp + ch * (HWN / 4);
#pragma unroll
        for (int k = 0; k < 4; ++k) {
            int idx = threadIdx.x + k * 256;
            float4 dv = __ldg(&d4[idx]);
            float4 av = sA4[idx];
            acc[ch] += dv.x * av.x + dv.y * av.y + dv.z * av.z + dv.w * av.w;
        }
    }

    int lane = threadIdx.x & 31;
    int warp = threadIdx.x >> 5;
    __shared__ float red[8][CPB];
#pragma unroll
    for (int ch = 0; ch < CPB; ++ch) {
        float v = acc[ch];
#pragma unroll
        for (int o = 16; o > 0; o >>= 1) v += __shfl_down_sync(0xffffffffu, v, o);
        if (lane == 0) red[warp][ch] = v;
    }
    __syncthreads();

    if (threadIdx.x < CPB) {
        float s = 0.0f;
#pragma unroll
        for (int w = 0; w < 8; ++w) s += red[w][threadIdx.x];
        out[b * CC + cg * CPB + threadIdx.x] = s;
    }
}

extern "C" void kernel_launch(void* const* d_in, const int* in_sizes, int n_in,
                              void* d_out, int out_size)
{
    const float* data   = (const float*)d_in[0];   // [32,256,64,64]
    const float* offset = (const float*)d_in[1];   // [32,2,64,64]
    const float* ts     = (const float*)d_in[2];   // scalar
    float* out = (float*)d_out;                    // [32,256]

    zero_A_kernel<<<(BB * HWN + 255) / 256, 256>>>();
    scatter_kernel<<<dim3(8, BB), 256>>>(offset, ts);
    dot_kernel<<<BB * (CC / CPB), 256>>>(data, out);
}